// round 7
// baseline (speedup 1.0000x reference)
#include <cuda_runtime.h>
#include <cuda_bf16.h>
#include <math.h>
#include <stdint.h>

// ---------------------------------------------------------------------------
// GCN encoder on GB300: mma.sync bf16x3 GEMMs + CSR gather aggregation.
// All intermediates stored as hi/lo bf16 planes (fp32-class accuracy, zero
// conversion cost in GEMM staging via cp.async).
// ---------------------------------------------------------------------------

#define NMAX 100000
#define NPAD 100224      // padded to multiple of 128 rows
#define EMAX 2000000

__device__ int   g_deg[NMAX];
__device__ int   g_rs[NMAX];
__device__ int   g_cursor[NMAX];
__device__ int   g_blk[512];
__device__ int   g_csrc[EMAX];
__device__ float g_cnrm[EMAX];
__device__ __nv_bfloat16 g_hiA[(size_t)NPAD * 128];
__device__ __nv_bfloat16 g_loA[(size_t)NPAD * 128];
__device__ __nv_bfloat16 g_hiB[(size_t)NPAD * 128];
__device__ __nv_bfloat16 g_loB[(size_t)NPAD * 128];
__device__ __nv_bfloat16 g_hiC[(size_t)NPAD * 128];
__device__ __nv_bfloat16 g_loC[(size_t)NPAD * 128];
__device__ uint32_t g_wfrag[6 * 16384];

// ------------------------------ small helpers ------------------------------

__device__ __forceinline__ uint32_t smem_u32(const void* p) {
    uint32_t a;
    asm("{ .reg .u64 t; cvta.to.shared.u64 t, %1; cvt.u32.u64 %0, t; }" : "=r"(a) : "l"(p));
    return a;
}

__device__ __forceinline__ void cp16(uint32_t s, const void* g) {
    asm volatile("cp.async.ca.shared.global [%0], [%1], 16;" :: "r"(s), "l"(g));
}
#define CP_COMMIT() asm volatile("cp.async.commit_group;" ::: "memory")
#define CP_WAIT()   asm volatile("cp.async.wait_group 0;" ::: "memory")

// load 4 consecutive cols from hi/lo planes -> fp32
__device__ __forceinline__ float4 ld_hilo4(const __nv_bfloat16* __restrict__ hi,
                                           const __nv_bfloat16* __restrict__ lo,
                                           size_t off) {
    uint2 hw = __ldg((const uint2*)(hi + off));
    uint2 lw = __ldg((const uint2*)(lo + off));
    __nv_bfloat162 h0 = *(__nv_bfloat162*)&hw.x, h1 = *(__nv_bfloat162*)&hw.y;
    __nv_bfloat162 l0 = *(__nv_bfloat162*)&lw.x, l1 = *(__nv_bfloat162*)&lw.y;
    float4 v;
    v.x = __bfloat162float(h0.x) + __bfloat162float(l0.x);
    v.y = __bfloat162float(h0.y) + __bfloat162float(l0.y);
    v.z = __bfloat162float(h1.x) + __bfloat162float(l1.x);
    v.w = __bfloat162float(h1.y) + __bfloat162float(l1.y);
    return v;
}

// store 4 fp32 values as hi/lo bf16
__device__ __forceinline__ void st_hilo4(__nv_bfloat16* __restrict__ hi,
                                         __nv_bfloat16* __restrict__ lo,
                                         size_t off, float4 v) {
    __nv_bfloat162 h0, h1, l0, l1;
    h0.x = __float2bfloat16(v.x); h0.y = __float2bfloat16(v.y);
    h1.x = __float2bfloat16(v.z); h1.y = __float2bfloat16(v.w);
    l0.x = __float2bfloat16(v.x - __bfloat162float(h0.x));
    l0.y = __float2bfloat16(v.y - __bfloat162float(h0.y));
    l1.x = __float2bfloat16(v.z - __bfloat162float(h1.x));
    l1.y = __float2bfloat16(v.w - __bfloat162float(h1.y));
    uint2 hw = make_uint2(*(uint32_t*)&h0, *(uint32_t*)&h1);
    uint2 lw = make_uint2(*(uint32_t*)&l0, *(uint32_t*)&l1);
    *(uint2*)(hi + off) = hw;
    *(uint2*)(lo + off) = lw;
}

// ------------------------------ CSR build ----------------------------------

__global__ void deg_zero_kernel(int* __restrict__ deg, int n) {
    int i = blockIdx.x * 256 + threadIdx.x;
    if (i < n) deg[i] = 0;
}

__global__ void deg_count_kernel(const int* __restrict__ dst, int* __restrict__ deg, int E) {
    int e = blockIdx.x * 256 + threadIdx.x;
    if (e < E) atomicAdd(&deg[dst[e]], 1);
}

__global__ void scan1_kernel(const int* __restrict__ deg, int* __restrict__ tmp,
                             int* __restrict__ blk, int n) {
    __shared__ int sh[256];
    int tid = threadIdx.x;
    int i = blockIdx.x * 256 + tid;
    int v = (i < n) ? deg[i] : 0;
    sh[tid] = v;
    __syncthreads();
#pragma unroll
    for (int off = 1; off < 256; off <<= 1) {
        int t = (tid >= off) ? sh[tid - off] : 0;
        __syncthreads();
        sh[tid] += t;
        __syncthreads();
    }
    if (i < n) tmp[i] = sh[tid];
    if (tid == 255) blk[blockIdx.x] = sh[255];
}

__global__ void scan2_kernel(int* __restrict__ blk, int nb) {
    if (threadIdx.x == 0 && blockIdx.x == 0) {
        int run = 0;
        for (int b = 0; b < nb; b++) {
            int t = blk[b];
            blk[b] = run;
            run += t;
        }
    }
}

__global__ void scan3_kernel(const int* __restrict__ tmp, const int* __restrict__ deg,
                             const int* __restrict__ blk, int* __restrict__ rs,
                             int* __restrict__ cursor, int n) {
    int i = blockIdx.x * 256 + threadIdx.x;
    if (i < n) {
        int v = tmp[i] - deg[i] + blk[blockIdx.x];
        rs[i] = v;
        cursor[i] = v;
    }
}

__global__ void scatter_kernel(const int* __restrict__ src, const int* __restrict__ dst,
                               const int* __restrict__ deg, int* __restrict__ cursor,
                               int* __restrict__ csrc, float* __restrict__ cnrm, int E) {
    int e = blockIdx.x * 256 + threadIdx.x;
    if (e >= E) return;
    int s = __ldg(&src[e]);
    int d = __ldg(&dst[e]);
    int pos = atomicAdd(&cursor[d], 1);
    csrc[pos] = s;
    cnrm[pos] = rsqrtf((float)(__ldg(&deg[s]) + 1)) * rsqrtf((float)(__ldg(&deg[d]) + 1));
}

// ---------------------- CSR gather aggregation -----------------------------
// out[d] = act((BIAS? b : 0) + h[d]/(deg[d]+1) + sum_adj h[src]*nrm), hi/lo IO.
// D = feature dim (stride), LN = lanes per node = D/4.

template <int D, bool BIAS, bool RELU>
__global__ void csr_agg_kernel(const int* __restrict__ rs, const int* __restrict__ deg,
                               const int* __restrict__ csrc, const float* __restrict__ cnrm,
                               const float* __restrict__ bias,
                               const __nv_bfloat16* __restrict__ hi,
                               const __nv_bfloat16* __restrict__ lo,
                               __nv_bfloat16* __restrict__ ohi,
                               __nv_bfloat16* __restrict__ olo, int n) {
    constexpr int LN = D / 4;
    int t = blockIdx.x * 256 + threadIdx.x;
    int d = t / LN;
    int lane = t % LN;
    if (d >= n) return;
    int start = __ldg(&rs[d]);
    int dg = __ldg(&deg[d]);
    float inv = 1.0f / (float)(dg + 1);
    size_t coff = (size_t)lane * 4;
    float4 acc = ld_hilo4(hi, lo, (size_t)d * D + coff);
    acc.x *= inv; acc.y *= inv; acc.z *= inv; acc.w *= inv;
    if (BIAS) {
        float4 b = *(const float4*)(bias + coff);
        acc.x += b.x; acc.y += b.y; acc.z += b.z; acc.w += b.w;
    }
    int j = start, end = start + dg;
    for (; j + 2 <= end; j += 2) {
        int s0 = __ldg(&csrc[j]), s1 = __ldg(&csrc[j + 1]);
        float n0 = __ldg(&cnrm[j]), n1 = __ldg(&cnrm[j + 1]);
        float4 v0 = ld_hilo4(hi, lo, (size_t)s0 * D + coff);
        float4 v1 = ld_hilo4(hi, lo, (size_t)s1 * D + coff);
        acc.x += v0.x * n0 + v1.x * n1;
        acc.y += v0.y * n0 + v1.y * n1;
        acc.z += v0.z * n0 + v1.z * n1;
        acc.w += v0.w * n0 + v1.w * n1;
    }
    if (j < end) {
        int s0 = __ldg(&csrc[j]);
        float n0 = __ldg(&cnrm[j]);
        float4 v0 = ld_hilo4(hi, lo, (size_t)s0 * D + coff);
        acc.x += v0.x * n0; acc.y += v0.y * n0;
        acc.z += v0.z * n0; acc.w += v0.w * n0;
    }
    if (RELU) {
        acc.x = fmaxf(acc.x, 0.f); acc.y = fmaxf(acc.y, 0.f);
        acc.z = fmaxf(acc.z, 0.f); acc.w = fmaxf(acc.w, 0.f);
    }
    st_hilo4(ohi, olo, (size_t)d * D + coff, acc);
}

// ------------------------- weight fragment packing --------------------------

__global__ void wprep_all_kernel(const float* __restrict__ w0, const float* __restrict__ w1,
                                 const float* __restrict__ w2, const float* __restrict__ w3,
                                 const float* __restrict__ w4, const float* __restrict__ w5,
                                 uint32_t* __restrict__ wf) {
    int idx = blockIdx.x * 256 + threadIdx.x;
    int tile = idx >> 5;
    if (tile >= 544) return;
    int lane = idx & 31;

    const float* W;
    int K, N, slot, base;
    bool TR;
    if (tile < 128)      { slot = 0; base = 0;   W = w0; K = 128; N = 128; TR = true;  }
    else if (tile < 256) { slot = 1; base = 128; W = w1; K = 128; N = 128; TR = false; }
    else if (tile < 320) { slot = 2; base = 256; W = w2; K = 128; N = 64;  TR = true;  }
    else if (tile < 352) { slot = 3; base = 320; W = w3; K = 64;  N = 64;  TR = false; }
    else if (tile < 416) { slot = 4; base = 352; W = w4; K = 64;  N = 128; TR = true;  }
    else                 { slot = 5; base = 416; W = w5; K = 128; N = 128; TR = false; }

    int t = tile - base;
    int NT = N / 8;
    int nt = t % NT;
    int kt = t / NT;
    int g = lane >> 2, tig = lane & 3;
    int nn = nt * 8 + g;
    uint32_t* out = wf + slot * 16384;
    int LOFF = K * N / 2;

#pragma unroll
    for (int r = 0; r < 2; r++) {
        int k0 = kt * 16 + tig * 2 + r * 8;
        float v0 = TR ? W[(size_t)k0 * N + nn] : W[(size_t)nn * K + k0];
        float v1 = TR ? W[(size_t)(k0 + 1) * N + nn] : W[(size_t)nn * K + k0 + 1];
        __nv_bfloat16 h0 = __float2bfloat16(v0), h1 = __float2bfloat16(v1);
        float l0 = v0 - __bfloat162float(h0), l1 = v1 - __bfloat162float(h1);
        __nv_bfloat162 hp; hp.x = h0; hp.y = h1;
        __nv_bfloat162 lp; lp.x = __float2bfloat16(l0); lp.y = __float2bfloat16(l1);
        out[(size_t)(t * 32 + lane) * 2 + r] = *(uint32_t*)&hp;
        out[LOFF + (size_t)(t * 32 + lane) * 2 + r] = *(uint32_t*)&lp;
    }
}

// --------------------------------- MMA GEMM --------------------------------
// C = epi(act-free A[hi/lo or f32] @ B) via bf16 split-3.
// F32IN: input is fp32 (convert+guard); else hi/lo planes via cp.async.
// EPI: 0 = raw, 1 = relu(A + d) (K==N), 2 = relu(d + bias)
// OUTF32: write fp32 (final layer) else hi/lo planes.

__device__ __forceinline__ void mma_bf16(float* c, const uint32_t* a, uint32_t b0, uint32_t b1) {
    asm volatile(
        "mma.sync.aligned.m16n8k16.row.col.f32.bf16.bf16.f32 "
        "{%0,%1,%2,%3}, {%4,%5,%6,%7}, {%8,%9}, {%0,%1,%2,%3};"
        : "+f"(c[0]), "+f"(c[1]), "+f"(c[2]), "+f"(c[3])
        : "r"(a[0]), "r"(a[1]), "r"(a[2]), "r"(a[3]), "r"(b0), "r"(b1));
}

__device__ __forceinline__ void ldsm_x4(uint32_t* r, uint32_t addr) {
    asm volatile("ldmatrix.sync.aligned.m8n8.x4.shared.b16 {%0,%1,%2,%3}, [%4];"
                 : "=r"(r[0]), "=r"(r[1]), "=r"(r[2]), "=r"(r[3]) : "r"(addr));
}

template <int K, int N, bool F32IN, int EPI, bool OUTF32>
__global__ __launch_bounds__(256, 2) void mma_gemm_kernel(
    const float* __restrict__ A32,
    const __nv_bfloat16* __restrict__ Ahi, const __nv_bfloat16* __restrict__ Alo,
    const uint32_t* __restrict__ WF,
    float* __restrict__ C32,
    __nv_bfloat16* __restrict__ Chi, __nv_bfloat16* __restrict__ Clo,
    const float* __restrict__ bias, int n) {
    constexpr int LDA = K + 8;
    constexpr int NT = N / 8;
    constexpr int KT = K / 16;
    constexpr int WN = N / 64;
    constexpr int WM = 8 / WN;
    constexpr int MT = 128 / (WM * 16);
    constexpr int LOFF = K * N / 2;

    extern __shared__ __align__(16) char smem[];
    __nv_bfloat16* Ah = (__nv_bfloat16*)smem;
    __nv_bfloat16* Al = Ah + 128 * LDA;

    const int tid = threadIdx.x;
    const int w = tid >> 5;
    const int lane = tid & 31;
    const int g = lane >> 2, tig = lane & 3;
    const int row0 = blockIdx.x * 128;
    const int wm = w / WN;
    const int wn = w % WN;
    const uint32_t smem_base = smem_u32(smem);

    // ---- stage A ----
    if (F32IN) {
        constexpr int KQ = K / 4;
        for (int idx = tid; idx < 128 * KQ; idx += 256) {
            int r = idx / KQ;
            int k0 = (idx - r * KQ) * 4;
            float4 v = make_float4(0.f, 0.f, 0.f, 0.f);
            if (row0 + r < n) v = *(const float4*)(A32 + (size_t)(row0 + r) * K + k0);
            __nv_bfloat16 h0 = __float2bfloat16(v.x), h1 = __float2bfloat16(v.y);
            __nv_bfloat16 h2 = __float2bfloat16(v.z), h3 = __float2bfloat16(v.w);
            __nv_bfloat162 hp0; hp0.x = h0; hp0.y = h1;
            __nv_bfloat162 hp1; hp1.x = h2; hp1.y = h3;
            __nv_bfloat162 lp0, lp1;
            lp0.x = __float2bfloat16(v.x - __bfloat162float(h0));
            lp0.y = __float2bfloat16(v.y - __bfloat162float(h1));
            lp1.x = __float2bfloat16(v.z - __bfloat162float(h2));
            lp1.y = __float2bfloat16(v.w - __bfloat162float(h3));
            *(uint2*)(Ah + r * LDA + k0) = make_uint2(*(uint32_t*)&hp0, *(uint32_t*)&hp1);
            *(uint2*)(Al + r * LDA + k0) = make_uint2(*(uint32_t*)&lp0, *(uint32_t*)&lp1);
        }
        __syncthreads();
    } else {
        // cp.async: 16B chunks (8 bf16 cols), rows padded so no guard needed
        constexpr int CH = K / 8;
        const uint32_t loff = (uint32_t)(128 * LDA * 2);
        for (int idx = tid; idx < 128 * CH; idx += 256) {
            int r = idx / CH;
            int c = idx - r * CH;
            uint32_t so = smem_base + (uint32_t)((r * LDA + c * 8) * 2);
            size_t go = (size_t)(row0 + r) * K + c * 8;
            cp16(so, Ahi + go);
            cp16(so + loff, Alo + go);
        }
        CP_COMMIT();
        CP_WAIT();
        __syncthreads();
    }

    // ---- mainloop ----
    float acc[MT][8][4];
#pragma unroll
    for (int mt = 0; mt < MT; mt++)
#pragma unroll
        for (int nt = 0; nt < 8; nt++)
#pragma unroll
            for (int i = 0; i < 4; i++) acc[mt][nt][i] = 0.f;

    const uint32_t a_base =
        smem_base + (uint32_t)(((wm * MT * 16 + (lane & 15)) * LDA + (lane >> 4) * 8) * 2);
    const uint32_t l_base = a_base + (uint32_t)(128 * LDA * 2);

#pragma unroll
    for (int kt = 0; kt < KT; kt++) {
        uint32_t ah[MT][4], al[MT][4];
#pragma unroll
        for (int mt = 0; mt < MT; mt++) {
            uint32_t off = (uint32_t)((mt * 16 * LDA + kt * 16) * 2);
            ldsm_x4(ah[mt], a_base + off);
            ldsm_x4(al[mt], l_base + off);
        }
#pragma unroll
        for (int nt = 0; nt < 8; nt++) {
            int gnt = wn * 8 + nt;
            const uint32_t* bp = WF + ((size_t)(kt * NT + gnt) * 32 + lane) * 2;
            uint2 bh = *(const uint2*)bp;
            uint2 bl = *(const uint2*)(bp + LOFF);
#pragma unroll
            for (int mt = 0; mt < MT; mt++) {
                mma_bf16(acc[mt][nt], ah[mt], bh.x, bh.y);
                mma_bf16(acc[mt][nt], ah[mt], bl.x, bl.y);
                mma_bf16(acc[mt][nt], al[mt], bh.x, bh.y);
            }
        }
    }

    // ---- epilogue ----
#pragma unroll
    for (int mt = 0; mt < MT; mt++) {
        int rbase = wm * MT * 16 + mt * 16;
#pragma unroll
        for (int h = 0; h < 2; h++) {
            int rloc = rbase + g + h * 8;
            int row = row0 + rloc;
            if (row >= n) continue;
#pragma unroll
            for (int nt = 0; nt < 8; nt++) {
                int col = wn * 64 + nt * 8 + tig * 2;
                float v0 = acc[mt][nt][h * 2 + 0];
                float v1 = acc[mt][nt][h * 2 + 1];
                if (EPI == 1) {
                    __nv_bfloat162 rh = *(const __nv_bfloat162*)(Ah + rloc * LDA + col);
                    __nv_bfloat162 rl = *(const __nv_bfloat162*)(Al + rloc * LDA + col);
                    v0 = fmaxf(v0 + __bfloat162float(rh.x) + __bfloat162float(rl.x), 0.f);
                    v1 = fmaxf(v1 + __bfloat162float(rh.y) + __bfloat162float(rl.y), 0.f);
                } else if (EPI == 2) {
                    v0 = fmaxf(v0 + __ldg(&bias[col]), 0.f);
                    v1 = fmaxf(v1 + __ldg(&bias[col + 1]), 0.f);
                }
                size_t off = (size_t)row * N + col;
                if (OUTF32) {
                    float2 o; o.x = v0; o.y = v1;
                    *(float2*)(C32 + off) = o;
                } else {
                    __nv_bfloat162 hp, lp;
                    hp.x = __float2bfloat16(v0);
                    hp.y = __float2bfloat16(v1);
                    lp.x = __float2bfloat16(v0 - __bfloat162float(hp.x));
                    lp.y = __float2bfloat16(v1 - __bfloat162float(hp.y));
                    *(uint32_t*)(Chi + off) = *(uint32_t*)&hp;
                    *(uint32_t*)(Clo + off) = *(uint32_t*)&lp;
                }
            }
        }
    }
}

template <int K, int N, bool F32IN, int EPI, bool OUTF32>
static void launch_mma(const float* A32, const __nv_bfloat16* Ahi, const __nv_bfloat16* Alo,
                       const uint32_t* WF, float* C32, __nv_bfloat16* Chi, __nv_bfloat16* Clo,
                       const float* bias, int n) {
    constexpr int SMEM = 2 * 128 * (K + 8) * 2;
    auto kfn = mma_gemm_kernel<K, N, F32IN, EPI, OUTF32>;
    if (SMEM > 48 * 1024)
        cudaFuncSetAttribute(kfn, cudaFuncAttributeMaxDynamicSharedMemorySize, SMEM);
    kfn<<<(n + 127) / 128, 256, SMEM>>>(A32, Ahi, Alo, WF, C32, Chi, Clo, bias, n);
}

// --------------------------------- driver ----------------------------------

extern "C" void kernel_launch(void* const* d_in, const int* in_sizes, int n_in,
                              void* d_out, int out_size) {
    const float* x    = (const float*)d_in[0];
    const int*   ei   = (const int*)d_in[1];
    const float* g1w  = (const float*)d_in[2];
    const float* g1b  = (const float*)d_in[3];
    const float* fc2w = (const float*)d_in[4];
    const float* g3w  = (const float*)d_in[5];
    const float* g3b  = (const float*)d_in[6];
    const float* fc4w = (const float*)d_in[7];
    const float* g5w  = (const float*)d_in[8];
    const float* g5b  = (const float*)d_in[9];
    const float* fc6w = (const float*)d_in[10];

    int n = in_sizes[0] / 128;
    int E = in_sizes[1] / 2;
    const int* src = ei;
    const int* dst = ei + E;
    int nb = (n + 255) / 256;

    int *deg, *rs, *cursor, *blk, *csrc;
    float* cnrm;
    __nv_bfloat16 *hiA, *loA, *hiB, *loB, *hiC, *loC;
    uint32_t* wf;
    cudaGetSymbolAddress((void**)&deg, g_deg);
    cudaGetSymbolAddress((void**)&rs, g_rs);
    cudaGetSymbolAddress((void**)&cursor, g_cursor);
    cudaGetSymbolAddress((void**)&blk, g_blk);
    cudaGetSymbolAddress((void**)&csrc, g_csrc);
    cudaGetSymbolAddress((void**)&cnrm, g_cnrm);
    cudaGetSymbolAddress((void**)&hiA, g_hiA);
    cudaGetSymbolAddress((void**)&loA, g_loA);
    cudaGetSymbolAddress((void**)&hiB, g_hiB);
    cudaGetSymbolAddress((void**)&loB, g_loB);
    cudaGetSymbolAddress((void**)&hiC, g_hiC);
    cudaGetSymbolAddress((void**)&loC, g_loC);
    cudaGetSymbolAddress((void**)&wf, g_wfrag);
    uint32_t* wf0 = wf;
    uint32_t* wf1 = wf + 16384;
    uint32_t* wf2 = wf + 2 * 16384;
    uint32_t* wf3 = wf + 3 * 16384;
    uint32_t* wf4 = wf + 4 * 16384;
    uint32_t* wf5 = wf + 5 * 16384;

    // ---- prep ----
    wprep_all_kernel<<<68, 256>>>(g1w, fc2w, g3w, fc4w, g5w, fc6w, wf);
    deg_zero_kernel<<<nb, 256>>>(deg, n);
    deg_count_kernel<<<(E + 255) / 256, 256>>>(dst, deg, E);
    scan1_kernel<<<nb, 256>>>(deg, cursor, blk, n);
    scan2_kernel<<<1, 32>>>(blk, nb);
    scan3_kernel<<<nb, 256>>>(cursor, deg, blk, rs, cursor, n);
    scatter_kernel<<<(E + 255) / 256, 256>>>(src, dst, deg, cursor, csrc, cnrm, E);

    // ---- layer 1 ----
    // A = h1 = x @ W1 (raw hi/lo)
    launch_mma<128, 128, true, 0, false>(x, nullptr, nullptr, wf0, nullptr, hiA, loA, nullptr, n);
    // B = z1 = relu(agg(A) + b1)
    csr_agg_kernel<128, true, true><<<(n * 32 + 255) / 256, 256>>>(
        rs, deg, csrc, cnrm, g1b, hiA, loA, hiB, loB, n);
    // A = z1' = relu(B + B @ fc2^T)
    launch_mma<128, 128, false, 1, false>(nullptr, hiB, loB, wf1, nullptr, hiA, loA, nullptr, n);

    // ---- layer 2 ----
    // B = h2 = z1' @ W3 (raw, d=64)
    launch_mma<128, 64, false, 0, false>(nullptr, hiA, loA, wf2, nullptr, hiB, loB, nullptr, n);
    // C = z2 = relu(agg(B) + b3)
    csr_agg_kernel<64, true, true><<<(n * 16 + 255) / 256, 256>>>(
        rs, deg, csrc, cnrm, g3b, hiB, loB, hiC, loC, n);
    // A = z2' = relu(C + C @ fc4^T)
    launch_mma<64, 64, false, 1, false>(nullptr, hiC, loC, wf3, nullptr, hiA, loA, nullptr, n);

    // ---- layer 3 (aggregate first at d=64) ----
    // B = agg(A) (raw)
    csr_agg_kernel<64, false, false><<<(n * 16 + 255) / 256, 256>>>(
        rs, deg, csrc, cnrm, nullptr, hiA, loA, hiB, loB, n);
    // C = z3 = relu(B @ W5 + b5)
    launch_mma<64, 128, false, 2, false>(nullptr, hiB, loB, wf4, nullptr, hiC, loC, g5b, n);
    // out = relu(C + C @ fc6^T), fp32
    launch_mma<128, 128, false, 1, true>(nullptr, hiC, loC, wf5, (float*)d_out, nullptr, nullptr,
                                         nullptr, n);
}

// round 8
// speedup vs baseline: 1.1544x; 1.1544x over previous
#include <cuda_runtime.h>
#include <cuda_bf16.h>
#include <math.h>
#include <stdint.h>

// ---------------------------------------------------------------------------
// GCN encoder on GB300: mma.sync bf16x3 GEMMs (fused pairs) + CSR gather agg.
// Intermediates stored INTERLEAVED hi/lo bf16 (one u32/elem): fp32-class
// accuracy, fp32-identical gather pattern, PRMT-cheap GEMM staging.
// ---------------------------------------------------------------------------

#define NMAX 100000
#define NPAD 100224
#define EMAX 2000000

__device__ int   g_deg[NMAX];
__device__ int   g_rs[NMAX];
__device__ int   g_cursor[NMAX];
__device__ int   g_blk[512];
__device__ int   g_csrc[EMAX];
__device__ float g_cnrm[EMAX];
__device__ uint32_t g_bufA[(size_t)NPAD * 128];
__device__ uint32_t g_bufB[(size_t)NPAD * 128];
__device__ uint32_t g_bufC[(size_t)NPAD * 128];
__device__ uint32_t g_wfrag[6 * 16384];

// ------------------------------ small helpers ------------------------------

__device__ __forceinline__ uint32_t smem_u32(const void* p) {
    uint32_t a;
    asm("{ .reg .u64 t; cvta.to.shared.u64 t, %1; cvt.u32.u64 %0, t; }" : "=r"(a) : "l"(p));
    return a;
}

__device__ __forceinline__ float il2f(uint32_t w) {
    __nv_bfloat162 p = *(__nv_bfloat162*)&w;
    return __bfloat162float(p.x) + __bfloat162float(p.y);
}

__device__ __forceinline__ uint32_t f2il(float v) {
    __nv_bfloat162 p;
    p.x = __float2bfloat16(v);
    p.y = __float2bfloat16(v - __bfloat162float(p.x));
    return *(uint32_t*)&p;
}

__device__ __forceinline__ void mma_bf16(float* c, const uint32_t* a, uint32_t b0, uint32_t b1) {
    asm volatile(
        "mma.sync.aligned.m16n8k16.row.col.f32.bf16.bf16.f32 "
        "{%0,%1,%2,%3}, {%4,%5,%6,%7}, {%8,%9}, {%0,%1,%2,%3};"
        : "+f"(c[0]), "+f"(c[1]), "+f"(c[2]), "+f"(c[3])
        : "r"(a[0]), "r"(a[1]), "r"(a[2]), "r"(a[3]), "r"(b0), "r"(b1));
}

__device__ __forceinline__ void ldsm_x4(uint32_t* r, uint32_t addr) {
    asm volatile("ldmatrix.sync.aligned.m8n8.x4.shared.b16 {%0,%1,%2,%3}, [%4];"
                 : "=r"(r[0]), "=r"(r[1]), "=r"(r[2]), "=r"(r[3]) : "r"(addr));
}

// ------------------------------ CSR build ----------------------------------

__global__ void deg_zero_kernel(int* __restrict__ deg, int n) {
    int i = blockIdx.x * 256 + threadIdx.x;
    if (i < n) deg[i] = 0;
}

__global__ void deg_count_kernel(const int* __restrict__ dst, int* __restrict__ deg, int E) {
    int e = blockIdx.x * 256 + threadIdx.x;
    if (e < E) atomicAdd(&deg[dst[e]], 1);
}

__global__ void scan1_kernel(const int* __restrict__ deg, int* __restrict__ tmp,
                             int* __restrict__ blk, int n) {
    __shared__ int sh[256];
    int tid = threadIdx.x;
    int i = blockIdx.x * 256 + tid;
    int v = (i < n) ? deg[i] : 0;
    sh[tid] = v;
    __syncthreads();
#pragma unroll
    for (int off = 1; off < 256; off <<= 1) {
        int t = (tid >= off) ? sh[tid - off] : 0;
        __syncthreads();
        sh[tid] += t;
        __syncthreads();
    }
    if (i < n) tmp[i] = sh[tid];
    if (tid == 255) blk[blockIdx.x] = sh[255];
}

__global__ void scan2_kernel(int* __restrict__ blk, int nb) {
    if (threadIdx.x == 0 && blockIdx.x == 0) {
        int run = 0;
        for (int b = 0; b < nb; b++) {
            int t = blk[b];
            blk[b] = run;
            run += t;
        }
    }
}

__global__ void scan3_kernel(const int* __restrict__ tmp, const int* __restrict__ deg,
                             const int* __restrict__ blk, int* __restrict__ rs,
                             int* __restrict__ cursor, int n) {
    int i = blockIdx.x * 256 + threadIdx.x;
    if (i < n) {
        int v = tmp[i] - deg[i] + blk[blockIdx.x];
        rs[i] = v;
        cursor[i] = v;
    }
}

__global__ void scatter_kernel(const int* __restrict__ src, const int* __restrict__ dst,
                               const int* __restrict__ deg, int* __restrict__ cursor,
                               int* __restrict__ csrc, float* __restrict__ cnrm, int E) {
    int e = blockIdx.x * 256 + threadIdx.x;
    if (e >= E) return;
    int s = __ldg(&src[e]);
    int d = __ldg(&dst[e]);
    int pos = atomicAdd(&cursor[d], 1);
    csrc[pos] = s;
    cnrm[pos] = rsqrtf((float)(__ldg(&deg[s]) + 1)) * rsqrtf((float)(__ldg(&deg[d]) + 1));
}

// ---------------------- CSR gather aggregation (interleaved IO) -------------

template <int D, bool BIAS, bool RELU>
__global__ void csr_agg_kernel(const int* __restrict__ rs, const int* __restrict__ deg,
                               const int* __restrict__ csrc, const float* __restrict__ cnrm,
                               const float* __restrict__ bias,
                               const uint32_t* __restrict__ h, uint32_t* __restrict__ out,
                               int n) {
    constexpr int LN = D / 4;
    int t = blockIdx.x * 256 + threadIdx.x;
    int d = t / LN;
    int lane = t % LN;
    if (d >= n) return;
    int start = __ldg(&rs[d]);
    int dg = __ldg(&deg[d]);
    float inv = 1.0f / (float)(dg + 1);
    size_t coff = (size_t)lane * 4;
    uint4 w = __ldg((const uint4*)(h + (size_t)d * D + coff));
    float4 acc;
    acc.x = il2f(w.x) * inv; acc.y = il2f(w.y) * inv;
    acc.z = il2f(w.z) * inv; acc.w = il2f(w.w) * inv;
    if (BIAS) {
        float4 b = *(const float4*)(bias + coff);
        acc.x += b.x; acc.y += b.y; acc.z += b.z; acc.w += b.w;
    }
    int j = start, end = start + dg;
    for (; j + 2 <= end; j += 2) {
        int s0 = __ldg(&csrc[j]), s1 = __ldg(&csrc[j + 1]);
        float n0 = __ldg(&cnrm[j]), n1 = __ldg(&cnrm[j + 1]);
        uint4 w0 = __ldg((const uint4*)(h + (size_t)s0 * D + coff));
        uint4 w1 = __ldg((const uint4*)(h + (size_t)s1 * D + coff));
        acc.x += il2f(w0.x) * n0 + il2f(w1.x) * n1;
        acc.y += il2f(w0.y) * n0 + il2f(w1.y) * n1;
        acc.z += il2f(w0.z) * n0 + il2f(w1.z) * n1;
        acc.w += il2f(w0.w) * n0 + il2f(w1.w) * n1;
    }
    if (j < end) {
        int s0 = __ldg(&csrc[j]);
        float n0 = __ldg(&cnrm[j]);
        uint4 w0 = __ldg((const uint4*)(h + (size_t)s0 * D + coff));
        acc.x += il2f(w0.x) * n0; acc.y += il2f(w0.y) * n0;
        acc.z += il2f(w0.z) * n0; acc.w += il2f(w0.w) * n0;
    }
    if (RELU) {
        acc.x = fmaxf(acc.x, 0.f); acc.y = fmaxf(acc.y, 0.f);
        acc.z = fmaxf(acc.z, 0.f); acc.w = fmaxf(acc.w, 0.f);
    }
    uint4 o;
    o.x = f2il(acc.x); o.y = f2il(acc.y); o.z = f2il(acc.z); o.w = f2il(acc.w);
    *(uint4*)(out + (size_t)d * D + coff) = o;
}

// ------------------------- weight fragment packing --------------------------

__global__ void wprep_all_kernel(const float* __restrict__ w0, const float* __restrict__ w1,
                                 const float* __restrict__ w2, const float* __restrict__ w3,
                                 const float* __restrict__ w4, const float* __restrict__ w5,
                                 uint32_t* __restrict__ wf) {
    int idx = blockIdx.x * 256 + threadIdx.x;
    int tile = idx >> 5;
    if (tile >= 544) return;
    int lane = idx & 31;

    const float* W;
    int K, N, slot, base;
    bool TR;
    if (tile < 128)      { slot = 0; base = 0;   W = w0; K = 128; N = 128; TR = true;  }
    else if (tile < 256) { slot = 1; base = 128; W = w1; K = 128; N = 128; TR = false; }
    else if (tile < 320) { slot = 2; base = 256; W = w2; K = 128; N = 64;  TR = true;  }
    else if (tile < 352) { slot = 3; base = 320; W = w3; K = 64;  N = 64;  TR = false; }
    else if (tile < 416) { slot = 4; base = 352; W = w4; K = 64;  N = 128; TR = true;  }
    else                 { slot = 5; base = 416; W = w5; K = 128; N = 128; TR = false; }

    int t = tile - base;
    int NT = N / 8;
    int nt = t % NT;
    int kt = t / NT;
    int g = lane >> 2, tig = lane & 3;
    int nn = nt * 8 + g;
    uint32_t* out = wf + slot * 16384;
    int LOFF = K * N / 2;

#pragma unroll
    for (int r = 0; r < 2; r++) {
        int k0 = kt * 16 + tig * 2 + r * 8;
        float v0 = TR ? W[(size_t)k0 * N + nn] : W[(size_t)nn * K + k0];
        float v1 = TR ? W[(size_t)(k0 + 1) * N + nn] : W[(size_t)nn * K + k0 + 1];
        __nv_bfloat16 h0 = __float2bfloat16(v0), h1 = __float2bfloat16(v1);
        float l0 = v0 - __bfloat162float(h0), l1 = v1 - __bfloat162float(h1);
        __nv_bfloat162 hp; hp.x = h0; hp.y = h1;
        __nv_bfloat162 lp; lp.x = __float2bfloat16(l0); lp.y = __float2bfloat16(l1);
        out[(size_t)(t * 32 + lane) * 2 + r] = *(uint32_t*)&hp;
        out[LOFF + (size_t)(t * 32 + lane) * 2 + r] = *(uint32_t*)&lp;
    }
}

// ----------------------------- GEMM mainloop --------------------------------

template <int LDA, int KT, int NT, int MT>
__device__ __forceinline__ void gemm_mainloop(uint32_t a_base, uint32_t l_base,
                                              const uint32_t* __restrict__ WF,
                                              int wn, int lane, float (*acc)[8][4]) {
    constexpr int LOFF = KT * NT * 64;
#pragma unroll
    for (int kt = 0; kt < KT; kt++) {
        uint32_t ah[MT][4], al[MT][4];
#pragma unroll
        for (int mt = 0; mt < MT; mt++) {
            uint32_t off = (uint32_t)((mt * 16 * LDA + kt * 16) * 2);
            ldsm_x4(ah[mt], a_base + off);
            ldsm_x4(al[mt], l_base + off);
        }
#pragma unroll
        for (int nt = 0; nt < 8; nt++) {
            int gnt = wn * 8 + nt;
            const uint32_t* bp = WF + ((size_t)(kt * NT + gnt) * 32 + lane) * 2;
            uint2 bh = *(const uint2*)bp;
            uint2 bl = *(const uint2*)(bp + LOFF);
#pragma unroll
            for (int mt = 0; mt < MT; mt++) {
                mma_bf16(acc[mt][nt], ah[mt], bh.x, bh.y);
                mma_bf16(acc[mt][nt], ah[mt], bl.x, bl.y);
                mma_bf16(acc[mt][nt], al[mt], bh.x, bh.y);
            }
        }
    }
}

// ----------------------------- standard GEMM --------------------------------
// EPI: 0 = raw, 1 = relu(A + d) (K==N). Output interleaved.

template <int K, int N, bool F32IN, int EPI>
__global__ __launch_bounds__(256, 2) void mma_gemm_kernel(
    const float* __restrict__ A32, const uint32_t* __restrict__ Ail,
    const uint32_t* __restrict__ WF, uint32_t* __restrict__ Cil, int n) {
    constexpr int LDA = K + 8;
    constexpr int NT = N / 8;
    constexpr int KT = K / 16;
    constexpr int WN = N / 64;
    constexpr int WM = 8 / WN;
    constexpr int MT = 128 / (WM * 16);

    extern __shared__ __align__(16) char smem[];
    __nv_bfloat16* Ah = (__nv_bfloat16*)smem;
    __nv_bfloat16* Al = Ah + 128 * LDA;

    const int tid = threadIdx.x;
    const int w = tid >> 5;
    const int lane = tid & 31;
    const int g = lane >> 2, tig = lane & 3;
    const int row0 = blockIdx.x * 128;
    const int wm = w / WN;
    const int wn = w % WN;
    const uint32_t smem_base = smem_u32(smem);

    if (F32IN) {
        constexpr int KQ = K / 4;
        for (int idx = tid; idx < 128 * KQ; idx += 256) {
            int r = idx / KQ;
            int k0 = (idx - r * KQ) * 4;
            float4 v = make_float4(0.f, 0.f, 0.f, 0.f);
            if (row0 + r < n) v = *(const float4*)(A32 + (size_t)(row0 + r) * K + k0);
            uint32_t i0 = f2il(v.x), i1 = f2il(v.y), i2 = f2il(v.z), i3 = f2il(v.w);
            *(uint2*)(Ah + r * LDA + k0) =
                make_uint2(__byte_perm(i0, i1, 0x5410), __byte_perm(i2, i3, 0x5410));
            *(uint2*)(Al + r * LDA + k0) =
                make_uint2(__byte_perm(i0, i1, 0x7632), __byte_perm(i2, i3, 0x7632));
        }
    } else {
        constexpr int KW = K / 4;
        for (int idx = tid; idx < 128 * KW; idx += 256) {
            int r = idx / KW;
            int c4 = idx - r * KW;
            uint4 v = __ldg((const uint4*)(Ail + (size_t)(row0 + r) * K + c4 * 4));
            *(uint2*)(Ah + r * LDA + c4 * 4) =
                make_uint2(__byte_perm(v.x, v.y, 0x5410), __byte_perm(v.z, v.w, 0x5410));
            *(uint2*)(Al + r * LDA + c4 * 4) =
                make_uint2(__byte_perm(v.x, v.y, 0x7632), __byte_perm(v.z, v.w, 0x7632));
        }
    }
    __syncthreads();

    float acc[MT][8][4];
#pragma unroll
    for (int mt = 0; mt < MT; mt++)
#pragma unroll
        for (int nt = 0; nt < 8; nt++)
#pragma unroll
            for (int i = 0; i < 4; i++) acc[mt][nt][i] = 0.f;

    const uint32_t a_base =
        smem_base + (uint32_t)(((wm * MT * 16 + (lane & 15)) * LDA + (lane >> 4) * 8) * 2);
    const uint32_t l_base = a_base + (uint32_t)(128 * LDA * 2);
    gemm_mainloop<LDA, KT, NT, MT>(a_base, l_base, WF, wn, lane, acc);

#pragma unroll
    for (int mt = 0; mt < MT; mt++) {
        int rbase = wm * MT * 16 + mt * 16;
#pragma unroll
        for (int h = 0; h < 2; h++) {
            int rloc = rbase + g + h * 8;
            int row = row0 + rloc;
            if (row >= n) continue;
#pragma unroll
            for (int nt = 0; nt < 8; nt++) {
                int col = wn * 64 + nt * 8 + tig * 2;
                float v0 = acc[mt][nt][h * 2 + 0];
                float v1 = acc[mt][nt][h * 2 + 1];
                if (EPI == 1) {
                    __nv_bfloat162 rh = *(const __nv_bfloat162*)(Ah + rloc * LDA + col);
                    __nv_bfloat162 rl = *(const __nv_bfloat162*)(Al + rloc * LDA + col);
                    v0 = fmaxf(v0 + __bfloat162float(rh.x) + __bfloat162float(rl.x), 0.f);
                    v1 = fmaxf(v1 + __bfloat162float(rh.y) + __bfloat162float(rl.y), 0.f);
                }
                *(uint2*)(Cil + (size_t)row * N + col) = make_uint2(f2il(v0), f2il(v1));
            }
        }
    }
}

// ------------------------------ fused GEMM pair ------------------------------
// stage(Ail, K1) -> mma(WF1, N1) -> epi1 -> smem mid -> mma(WF2, N2) -> epi2.
// BIAS1: epi1 = relu(d + bias) (disjoint mid); else epi1 = relu(resid + d)
// in-place (K1==N1). OUTF32: epi2 = relu(mid + d) fp32; else raw interleaved.

template <int K1, int N1, int N2, bool BIAS1, bool OUTF32>
__global__ __launch_bounds__(256, 2) void fused_gemm_kernel(
    const uint32_t* __restrict__ Ail, const uint32_t* __restrict__ WF1,
    const uint32_t* __restrict__ WF2, float* __restrict__ C32,
    uint32_t* __restrict__ Cil, const float* __restrict__ bias1, int n) {
    constexpr int LDA1 = K1 + 8;
    constexpr int LDA2 = N1 + 8;
    constexpr bool INPLACE = !BIAS1;   // requires K1 == N1
    constexpr int KT1 = K1 / 16, NT1 = N1 / 8, WN1 = N1 / 64, WM1 = 8 / WN1,
                  MT1 = 128 / (WM1 * 16);
    constexpr int KT2 = N1 / 16, NT2 = N2 / 8, WN2 = N2 / 64, WM2 = 8 / WN2,
                  MT2 = 128 / (WM2 * 16);
    constexpr int MID_OFF = INPLACE ? 0 : 2 * 128 * LDA1;   // in bf16 elems

    extern __shared__ __align__(16) char smem[];
    __nv_bfloat16* Ah1 = (__nv_bfloat16*)smem;
    __nv_bfloat16* Al1 = Ah1 + 128 * LDA1;
    __nv_bfloat16* Ah2 = Ah1 + MID_OFF;
    __nv_bfloat16* Al2 = Ah2 + 128 * LDA2;

    const int tid = threadIdx.x;
    const int w = tid >> 5;
    const int lane = tid & 31;
    const int g = lane >> 2, tig = lane & 3;
    const int row0 = blockIdx.x * 128;
    const uint32_t smem_base = smem_u32(smem);

    // ---- stage from interleaved global (NPAD-padded, no guard) ----
    {
        constexpr int KW = K1 / 4;
        for (int idx = tid; idx < 128 * KW; idx += 256) {
            int r = idx / KW;
            int c4 = idx - r * KW;
            uint4 v = __ldg((const uint4*)(Ail + (size_t)(row0 + r) * K1 + c4 * 4));
            *(uint2*)(Ah1 + r * LDA1 + c4 * 4) =
                make_uint2(__byte_perm(v.x, v.y, 0x5410), __byte_perm(v.z, v.w, 0x5410));
            *(uint2*)(Al1 + r * LDA1 + c4 * 4) =
                make_uint2(__byte_perm(v.x, v.y, 0x7632), __byte_perm(v.z, v.w, 0x7632));
        }
    }
    __syncthreads();

    // ---- GEMM 1 ----
    {
        const int wm = w / WN1;
        const int wn = w % WN1;
        float acc[MT1][8][4];
#pragma unroll
        for (int mt = 0; mt < MT1; mt++)
#pragma unroll
            for (int nt = 0; nt < 8; nt++)
#pragma unroll
                for (int i = 0; i < 4; i++) acc[mt][nt][i] = 0.f;

        const uint32_t a_base =
            smem_base + (uint32_t)(((wm * MT1 * 16 + (lane & 15)) * LDA1 + (lane >> 4) * 8) * 2);
        const uint32_t l_base = a_base + (uint32_t)(128 * LDA1 * 2);
        gemm_mainloop<LDA1, KT1, NT1, MT1>(a_base, l_base, WF1, wn, lane, acc);

        if (INPLACE) __syncthreads();   // all mainloop-1 reads done before overwrite

        // epi1 -> mid planes (write all rows; garbage beyond n is discarded later)
#pragma unroll
        for (int mt = 0; mt < MT1; mt++) {
            int rbase = wm * MT1 * 16 + mt * 16;
#pragma unroll
            for (int h = 0; h < 2; h++) {
                int rloc = rbase + g + h * 8;
#pragma unroll
                for (int nt = 0; nt < 8; nt++) {
                    int col = wn * 64 + nt * 8 + tig * 2;
                    float v0 = acc[mt][nt][h * 2 + 0];
                    float v1 = acc[mt][nt][h * 2 + 1];
                    if (BIAS1) {
                        v0 = fmaxf(v0 + __ldg(&bias1[col]), 0.f);
                        v1 = fmaxf(v1 + __ldg(&bias1[col + 1]), 0.f);
                    } else {
                        __nv_bfloat162 rh = *(const __nv_bfloat162*)(Ah1 + rloc * LDA1 + col);
                        __nv_bfloat162 rl = *(const __nv_bfloat162*)(Al1 + rloc * LDA1 + col);
                        v0 = fmaxf(v0 + __bfloat162float(rh.x) + __bfloat162float(rl.x), 0.f);
                        v1 = fmaxf(v1 + __bfloat162float(rh.y) + __bfloat162float(rl.y), 0.f);
                    }
                    __nv_bfloat16 h0 = __float2bfloat16(v0), h1 = __float2bfloat16(v1);
                    __nv_bfloat162 hp; hp.x = h0; hp.y = h1;
                    __nv_bfloat162 lp;
                    lp.x = __float2bfloat16(v0 - __bfloat162float(h0));
                    lp.y = __float2bfloat16(v1 - __bfloat162float(h1));
                    *(uint32_t*)(Ah2 + rloc * LDA2 + col) = *(uint32_t*)&hp;
                    *(uint32_t*)(Al2 + rloc * LDA2 + col) = *(uint32_t*)&lp;
                }
            }
        }
    }
    __syncthreads();

    // ---- GEMM 2 ----
    {
        const int wm = w / WN2;
        const int wn = w % WN2;
        float acc[MT2][8][4];
#pragma unroll
        for (int mt = 0; mt < MT2; mt++)
#pragma unroll
            for (int nt = 0; nt < 8; nt++)
#pragma unroll
                for (int i = 0; i < 4; i++) acc[mt][nt][i] = 0.f;

        const uint32_t a_base = smem_base + (uint32_t)(MID_OFF * 2) +
            (uint32_t)(((wm * MT2 * 16 + (lane & 15)) * LDA2 + (lane >> 4) * 8) * 2);
        const uint32_t l_base = a_base + (uint32_t)(128 * LDA2 * 2);
        gemm_mainloop<LDA2, KT2, NT2, MT2>(a_base, l_base, WF2, wn, lane, acc);

#pragma unroll
        for (int mt = 0; mt < MT2; mt++) {
            int rbase = wm * MT2 * 16 + mt * 16;
#pragma unroll
            for (int h = 0; h < 2; h++) {
                int rloc = rbase + g + h * 8;
                int row = row0 + rloc;
                if (row >= n) continue;
#pragma unroll
                for (int nt = 0; nt < 8; nt++) {
                    int col = wn * 64 + nt * 8 + tig * 2;
                    float v0 = acc[mt][nt][h * 2 + 0];
                    float v1 = acc[mt][nt][h * 2 + 1];
                    if (OUTF32) {
                        __nv_bfloat162 rh = *(const __nv_bfloat162*)(Ah2 + rloc * LDA2 + col);
                        __nv_bfloat162 rl = *(const __nv_bfloat162*)(Al2 + rloc * LDA2 + col);
                        v0 = fmaxf(v0 + __bfloat162float(rh.x) + __bfloat162float(rl.x), 0.f);
                        v1 = fmaxf(v1 + __bfloat162float(rh.y) + __bfloat162float(rl.y), 0.f);
                        float2 o; o.x = v0; o.y = v1;
                        *(float2*)(C32 + (size_t)row * N2 + col) = o;
                    } else {
                        *(uint2*)(Cil + (size_t)row * N2 + col) = make_uint2(f2il(v0), f2il(v1));
                    }
                }
            }
        }
    }
}

// --------------------------------- launchers --------------------------------

template <int K, int N, bool F32IN, int EPI>
static void launch_std(const float* A32, const uint32_t* Ail, const uint32_t* WF,
                       uint32_t* Cil, int n) {
    constexpr int SMEM = 2 * 128 * (K + 8) * 2;
    auto kfn = mma_gemm_kernel<K, N, F32IN, EPI>;
    if (SMEM > 48 * 1024)
        cudaFuncSetAttribute(kfn, cudaFuncAttributeMaxDynamicSharedMemorySize, SMEM);
    kfn<<<(n + 127) / 128, 256, SMEM>>>(A32, Ail, WF, Cil, n);
}

template <int K1, int N1, int N2, bool BIAS1, bool OUTF32>
static void launch_fused(const uint32_t* Ail, const uint32_t* WF1, const uint32_t* WF2,
                         float* C32, uint32_t* Cil, const float* bias1, int n) {
    constexpr int SMEM = (BIAS1 ? (2 * 128 * (K1 + 8) + 2 * 128 * (N1 + 8))
                                : (2 * 128 * (K1 + 8))) * 2;
    auto kfn = fused_gemm_kernel<K1, N1, N2, BIAS1, OUTF32>;
    if (SMEM > 48 * 1024)
        cudaFuncSetAttribute(kfn, cudaFuncAttributeMaxDynamicSharedMemorySize, SMEM);
    kfn<<<(n + 127) / 128, 256, SMEM>>>(Ail, WF1, WF2, C32, Cil, bias1, n);
}

// --------------------------------- driver ----------------------------------

extern "C" void kernel_launch(void* const* d_in, const int* in_sizes, int n_in,
                              void* d_out, int out_size) {
    const float* x    = (const float*)d_in[0];
    const int*   ei   = (const int*)d_in[1];
    const float* g1w  = (const float*)d_in[2];
    const float* g1b  = (const float*)d_in[3];
    const float* fc2w = (const float*)d_in[4];
    const float* g3w  = (const float*)d_in[5];
    const float* g3b  = (const float*)d_in[6];
    const float* fc4w = (const float*)d_in[7];
    const float* g5w  = (const float*)d_in[8];
    const float* g5b  = (const float*)d_in[9];
    const float* fc6w = (const float*)d_in[10];

    int n = in_sizes[0] / 128;
    int E = in_sizes[1] / 2;
    const int* src = ei;
    const int* dst = ei + E;
    int nb = (n + 255) / 256;

    int *deg, *rs, *cursor, *blk, *csrc;
    float* cnrm;
    uint32_t *bA, *bB, *bC, *wf;
    cudaGetSymbolAddress((void**)&deg, g_deg);
    cudaGetSymbolAddress((void**)&rs, g_rs);
    cudaGetSymbolAddress((void**)&cursor, g_cursor);
    cudaGetSymbolAddress((void**)&blk, g_blk);
    cudaGetSymbolAddress((void**)&csrc, g_csrc);
    cudaGetSymbolAddress((void**)&cnrm, g_cnrm);
    cudaGetSymbolAddress((void**)&bA, g_bufA);
    cudaGetSymbolAddress((void**)&bB, g_bufB);
    cudaGetSymbolAddress((void**)&bC, g_bufC);
    cudaGetSymbolAddress((void**)&wf, g_wfrag);
    uint32_t* wf0 = wf;
    uint32_t* wf1 = wf + 16384;
    uint32_t* wf2 = wf + 2 * 16384;
    uint32_t* wf3 = wf + 3 * 16384;
    uint32_t* wf4 = wf + 4 * 16384;
    uint32_t* wf5 = wf + 5 * 16384;

    // ---- prep ----
    wprep_all_kernel<<<68, 256>>>(g1w, fc2w, g3w, fc4w, g5w, fc6w, wf);
    deg_zero_kernel<<<nb, 256>>>(deg, n);
    deg_count_kernel<<<(E + 255) / 256, 256>>>(dst, deg, E);
    scan1_kernel<<<nb, 256>>>(deg, cursor, blk, n);
    scan2_kernel<<<1, 32>>>(blk, nb);
    scan3_kernel<<<nb, 256>>>(cursor, deg, blk, rs, cursor, n);
    scatter_kernel<<<(E + 255) / 256, 256>>>(src, dst, deg, cursor, csrc, cnrm, E);

    // ---- layer 1 ----
    // A = h1 = x @ W1 (raw interleaved)
    launch_std<128, 128, true, 0>(x, nullptr, wf0, bA, n);
    // B = z1 = relu(agg(A) + b1)
    csr_agg_kernel<128, true, true><<<(n * 32 + 255) / 256, 256>>>(
        rs, deg, csrc, cnrm, g1b, bA, bB, n);
    // FUSED: z1' = relu(B + B@fc2^T); A = h2 = z1' @ W3 (d=64)
    launch_fused<128, 128, 64, false, false>(bB, wf1, wf2, nullptr, bA, nullptr, n);

    // ---- layer 2 ----
    // C = z2 = relu(agg(A) + b3)
    csr_agg_kernel<64, true, true><<<(n * 16 + 255) / 256, 256>>>(
        rs, deg, csrc, cnrm, g3b, bA, bC, n);
    // A = z2' = relu(C + C@fc4^T)
    launch_std<64, 64, false, 1>(nullptr, bC, wf3, bA, n);

    // ---- layer 3 (aggregate first at d=64) ----
    // B = agg(A) (raw)
    csr_agg_kernel<64, false, false><<<(n * 16 + 255) / 256, 256>>>(
        rs, deg, csrc, cnrm, nullptr, bA, bB, n);
    // FUSED: z3 = relu(B@W5 + b5); out = relu(z3 + z3@fc6^T) fp32
    launch_fused<64, 128, 128, true, true>(bB, wf4, wf5, (float*)d_out, nullptr, g5b, n);
}